// round 1
// baseline (speedup 1.0000x reference)
#include <cuda_runtime.h>
#include <cuda_bf16.h>
#include <stdint.h>

#define HEADS 16
#define MDIM 4096
#define NDIM 4096
#define KDIM 64
#define QBLK 32

// Quantized (dequantized-to-bf16, exact) operands. rhs is stored transposed: [h][n][k].
static __device__ __nv_bfloat16 g_lhs[(size_t)HEADS * MDIM * KDIM];
static __device__ __nv_bfloat16 g_rhs[(size_t)HEADS * NDIM * KDIM];

// ---------------------------------------------------------------------------
// BFP quantize one 32-element block in registers.
// Matches: e = floor(log2(max(maxabs,1e-38))); step = 2^(e-7);
//          q = clip(rint(x/step), -128, 127); out = maxabs>0 ? q*step : 0
// All steps are exact in fp32 (power-of-two scaling), and q*step has <= 8
// significant bits, hence exact in bf16.
// ---------------------------------------------------------------------------
__device__ __forceinline__ void quant_block32(float v[QBLK]) {
    float ma = 0.f;
#pragma unroll
    for (int i = 0; i < QBLK; i++) ma = fmaxf(ma, fabsf(v[i]));
    if (ma > 0.f) {
        int e = ilogbf(fmaxf(ma, 1e-38f));       // floor(log2(.)) exactly
        float scale = exp2f((float)(7 - e));     // exact power of two
        float step  = exp2f((float)(e - 7));
#pragma unroll
        for (int i = 0; i < QBLK; i++) {
            float q = rintf(v[i] * scale);       // round-half-even, exact scaling
            q = fminf(fmaxf(q, -128.f), 127.f);
            v[i] = q * step;                     // exact
        }
    } else {
#pragma unroll
        for (int i = 0; i < QBLK; i++) v[i] = 0.f;
    }
}

__device__ __forceinline__ void pack_store32(__nv_bfloat16* dst, const float v[QBLK]) {
    uint32_t pk[QBLK / 2];
#pragma unroll
    for (int j = 0; j < QBLK / 2; j++) {
        __nv_bfloat162 h2 = __floats2bfloat162_rn(v[2 * j], v[2 * j + 1]);
        pk[j] = *reinterpret_cast<uint32_t*>(&h2);
    }
    uint4* d4 = reinterpret_cast<uint4*>(dst);
#pragma unroll
    for (int j = 0; j < 4; j++)
        d4[j] = make_uint4(pk[4 * j], pk[4 * j + 1], pk[4 * j + 2], pk[4 * j + 3]);
}

// One thread per 32-block; lhs blocks are contiguous (K=64 is last axis).
__global__ void quant_lhs_kernel(const float* __restrict__ in) {
    size_t t = blockIdx.x * (size_t)blockDim.x + threadIdx.x;
    const float4* src = reinterpret_cast<const float4*>(in + t * QBLK);
    float v[QBLK];
#pragma unroll
    for (int j = 0; j < 8; j++) {
        float4 f = __ldg(src + j);
        v[4 * j] = f.x; v[4 * j + 1] = f.y; v[4 * j + 2] = f.z; v[4 * j + 3] = f.w;
    }
    quant_block32(v);
    pack_store32(g_lhs + t * QBLK, v);
}

// rhs is [h][k=64][n=4096]; BFP blocks run along k (stride NDIM in memory).
// Thread owns (h, kblock, n): reads 32 strided values (coalesced across lanes),
// writes 32 contiguous bf16 to transposed layout [h][n][k].
__global__ void quant_rhs_kernel(const float* __restrict__ in) {
    int t  = blockIdx.x * blockDim.x + threadIdx.x;
    int c  = t & (NDIM - 1);
    int kb = (t >> 12) & 1;
    int h  = t >> 13;
    const float* src = in + ((size_t)h * KDIM + kb * QBLK) * NDIM + c;
    float v[QBLK];
#pragma unroll
    for (int k = 0; k < QBLK; k++) v[k] = __ldg(src + (size_t)k * NDIM);
    quant_block32(v);
    pack_store32(g_rhs + (((size_t)h * NDIM + c) * KDIM + kb * QBLK), v);
}

// ---------------------------------------------------------------------------
// GEMM: out[h][m][n] = sum_k A[h][m][k] * B[h][n][k], bf16 in, fp32 out.
// 128x128 tile per CTA, whole K=64 resident in smem (no k-loop pipeline).
// 8 warps as 4(m) x 2(n); each warp computes 32x64 via m16n8k16 bf16 mma.
// ---------------------------------------------------------------------------
__global__ void __launch_bounds__(256, 1) bfp_gemm_kernel(float* __restrict__ out) {
    constexpr int BM = 128, BN = 128, PITCH = 72;  // 144B row pitch: conflict-free ldmatrix
    __shared__ __nv_bfloat16 sA[BM * PITCH];
    __shared__ __nv_bfloat16 sB[BN * PITCH];

    const int h  = blockIdx.z;
    const int bm = blockIdx.y, bn = blockIdx.x;
    const __nv_bfloat16* gA = g_lhs + ((size_t)h * MDIM + bm * BM) * KDIM;
    const __nv_bfloat16* gB = g_rhs + ((size_t)h * NDIM + bn * BN) * KDIM;
    const int tid = threadIdx.x;

    // 128 rows x 64 cols = 1024 uint4 per operand; 256 threads x 4 each.
#pragma unroll
    for (int i = 0; i < 4; i++) {
        int idx = tid + i * 256;
        int r = idx >> 3, vv = idx & 7;
        *reinterpret_cast<uint4*>(&sA[r * PITCH + vv * 8]) =
            *reinterpret_cast<const uint4*>(gA + r * KDIM + vv * 8);
        *reinterpret_cast<uint4*>(&sB[r * PITCH + vv * 8]) =
            *reinterpret_cast<const uint4*>(gB + r * KDIM + vv * 8);
    }
    __syncthreads();

    const int lane = tid & 31;
    const int wid  = tid >> 5;
    const int wm   = (wid >> 1) * 32;   // warp row base (0..96)
    const int wn   = (wid & 1) * 64;    // warp col base (0/64)

    float acc[2][8][4];
#pragma unroll
    for (int mt = 0; mt < 2; mt++)
#pragma unroll
        for (int nt = 0; nt < 8; nt++)
#pragma unroll
            for (int i = 0; i < 4; i++) acc[mt][nt][i] = 0.f;

#pragma unroll
    for (int ks = 0; ks < 4; ks++) {
        uint32_t a[2][4];
#pragma unroll
        for (int mt = 0; mt < 2; mt++) {
            int row = wm + mt * 16 + (lane & 15);
            int col = ks * 16 + (lane >> 4) * 8;
            uint32_t addr = (uint32_t)__cvta_generic_to_shared(&sA[row * PITCH + col]);
            asm volatile("ldmatrix.sync.aligned.m8n8.x4.shared.b16 {%0,%1,%2,%3}, [%4];\n"
                         : "=r"(a[mt][0]), "=r"(a[mt][1]), "=r"(a[mt][2]), "=r"(a[mt][3])
                         : "r"(addr));
        }
        uint32_t b[8][2];
#pragma unroll
        for (int nt = 0; nt < 8; nt++) {
            int row = wn + nt * 8 + (lane & 7);
            int col = ks * 16 + ((lane >> 3) & 1) * 8;
            uint32_t addr = (uint32_t)__cvta_generic_to_shared(&sB[row * PITCH + col]);
            asm volatile("ldmatrix.sync.aligned.m8n8.x2.shared.b16 {%0,%1}, [%2];\n"
                         : "=r"(b[nt][0]), "=r"(b[nt][1])
                         : "r"(addr));
        }
#pragma unroll
        for (int mt = 0; mt < 2; mt++)
#pragma unroll
            for (int nt = 0; nt < 8; nt++) {
                asm volatile(
                    "mma.sync.aligned.m16n8k16.row.col.f32.bf16.bf16.f32 "
                    "{%0,%1,%2,%3}, {%4,%5,%6,%7}, {%8,%9}, {%0,%1,%2,%3};\n"
                    : "+f"(acc[mt][nt][0]), "+f"(acc[mt][nt][1]),
                      "+f"(acc[mt][nt][2]), "+f"(acc[mt][nt][3])
                    : "r"(a[mt][0]), "r"(a[mt][1]), "r"(a[mt][2]), "r"(a[mt][3]),
                      "r"(b[nt][0]), "r"(b[nt][1]));
            }
    }

    // Direct global stores: every 32B sector fully utilized -> DRAM-write optimal.
    float* gO = out + (size_t)h * MDIM * NDIM + (size_t)(bm * BM) * NDIM + bn * BN;
#pragma unroll
    for (int mt = 0; mt < 2; mt++) {
#pragma unroll
        for (int nt = 0; nt < 8; nt++) {
            int r0 = wm + mt * 16 + (lane >> 2);
            int c0 = wn + nt * 8 + (lane & 3) * 2;
            *reinterpret_cast<float2*>(&gO[(size_t)r0 * NDIM + c0]) =
                make_float2(acc[mt][nt][0], acc[mt][nt][1]);
            *reinterpret_cast<float2*>(&gO[(size_t)(r0 + 8) * NDIM + c0]) =
                make_float2(acc[mt][nt][2], acc[mt][nt][3]);
        }
    }
}

extern "C" void kernel_launch(void* const* d_in, const int* in_sizes, int n_in,
                              void* d_out, int out_size) {
    (void)in_sizes; (void)n_in; (void)out_size;
    const float* lhs = (const float*)d_in[0];  // [1,16,4096,64]
    const float* rhs = (const float*)d_in[1];  // [1,16,64,4096]
    float* out = (float*)d_out;                // [1,16,4096,4096]

    // 16*4096*2 = 131072 quant blocks each
    quant_lhs_kernel<<<131072 / 256, 256>>>(lhs);
    quant_rhs_kernel<<<131072 / 256, 256>>>(rhs);

    dim3 grid(NDIM / 128, MDIM / 128, HEADS);
    bfp_gemm_kernel<<<grid, 256>>>(out);
}

// round 2
// speedup vs baseline: 1.0167x; 1.0167x over previous
#include <cuda_runtime.h>
#include <cuda_bf16.h>
#include <stdint.h>

#define HEADS 16
#define MDIM 4096
#define NDIM 4096
#define KDIM 64
#define QBLK 32

// Quantized (dequantized-to-bf16, exact) operands. rhs stored transposed: [h][n][k].
static __device__ __nv_bfloat16 g_lhs[(size_t)HEADS * MDIM * KDIM];
static __device__ __nv_bfloat16 g_rhs[(size_t)HEADS * NDIM * KDIM];

// ---------------------------------------------------------------------------
// Half-block (16-element) BFP quantize. Two adjacent threads own one 32-block;
// the shared block max comes from one shfl_xor. All arithmetic exact in fp32
// (power-of-two scaling); results have <=8 significant bits -> exact in bf16.
// ---------------------------------------------------------------------------
__device__ __forceinline__ void quant_half16(float v[16]) {
    float ma = 0.f;
#pragma unroll
    for (int i = 0; i < 16; i++) ma = fmaxf(ma, fabsf(v[i]));
    ma = fmaxf(ma, __shfl_xor_sync(0xFFFFFFFFu, ma, 1));  // full 32-block max
    if (ma > 0.f) {
        int e = ilogbf(fmaxf(ma, 1e-38f));       // floor(log2(.)) exactly
        float scale = exp2f((float)(7 - e));     // exact power of two
        float step  = exp2f((float)(e - 7));
#pragma unroll
        for (int i = 0; i < 16; i++) {
            float q = rintf(v[i] * scale);       // round-half-even
            q = fminf(fmaxf(q, -128.f), 127.f);
            v[i] = q * step;                     // exact
        }
    } else {
#pragma unroll
        for (int i = 0; i < 16; i++) v[i] = 0.f;
    }
}

__device__ __forceinline__ void pack_store16(__nv_bfloat16* dst, const float v[16]) {
    uint32_t pk[8];
#pragma unroll
    for (int j = 0; j < 8; j++) {
        __nv_bfloat162 h2 = __floats2bfloat162_rn(v[2 * j], v[2 * j + 1]);
        pk[j] = *reinterpret_cast<uint32_t*>(&h2);
    }
    uint4* d4 = reinterpret_cast<uint4*>(dst);
    d4[0] = make_uint4(pk[0], pk[1], pk[2], pk[3]);
    d4[1] = make_uint4(pk[4], pk[5], pk[6], pk[7]);
}

// lhs: [h][m][64] contiguous blocks. 2 threads per 32-block.
__global__ void quant_lhs_kernel(const float* __restrict__ in) {
    size_t t = blockIdx.x * (size_t)blockDim.x + threadIdx.x;
    const float4* src = reinterpret_cast<const float4*>(in + t * 16);
    float v[16];
#pragma unroll
    for (int j = 0; j < 4; j++) {
        float4 f = __ldg(src + j);
        v[4 * j] = f.x; v[4 * j + 1] = f.y; v[4 * j + 2] = f.z; v[4 * j + 3] = f.w;
    }
    quant_half16(v);
    pack_store16(g_lhs + t * 16, v);
}

// rhs: [h][k=64][n=4096]; BFP blocks along k (stride NDIM). 2 threads per block:
// same n-column, each covers 16 of the 32 k's. Reads coalesced across lanes.
__global__ void quant_rhs_kernel(const float* __restrict__ in) {
    int t    = blockIdx.x * blockDim.x + threadIdx.x;
    int half = t & 1;
    int pair = t >> 1;
    int c  = pair & (NDIM - 1);
    int kb = (pair >> 12) & 1;
    int h  = pair >> 13;
    const float* src = in + ((size_t)h * KDIM + kb * QBLK + half * 16) * NDIM + c;
    float v[16];
#pragma unroll
    for (int k = 0; k < 16; k++) v[k] = __ldg(src + (size_t)k * NDIM);
    quant_half16(v);
    pack_store16(g_rhs + (((size_t)h * NDIM + c) * KDIM + kb * QBLK + half * 16), v);
}

// ---------------------------------------------------------------------------
// GEMM: out[h][m][n] = sum_k A[h][m][k] * B[h][n][k], bf16 in, fp32 out.
// 128x128 tile per CTA, whole K=64 in smem. 8 warps = 4(m) x 2(n), each 32x64.
// 2 CTAs/SM so one CTA's MMAs overlap the other's load/store phases.
// ---------------------------------------------------------------------------
__global__ void __launch_bounds__(256, 2) bfp_gemm_kernel(float* __restrict__ out) {
    constexpr int BM = 128, BN = 128, PITCH = 72;  // 144B pitch: conflict-free ldmatrix
    __shared__ __nv_bfloat16 sA[BM * PITCH];
    __shared__ __nv_bfloat16 sB[BN * PITCH];

    const int h  = blockIdx.z;
    const int bm = blockIdx.y, bn = blockIdx.x;
    const __nv_bfloat16* gA = g_lhs + ((size_t)h * MDIM + bm * BM) * KDIM;
    const __nv_bfloat16* gB = g_rhs + ((size_t)h * NDIM + bn * BN) * KDIM;
    const int tid = threadIdx.x;

#pragma unroll
    for (int i = 0; i < 4; i++) {
        int idx = tid + i * 256;
        int r = idx >> 3, vv = idx & 7;
        *reinterpret_cast<uint4*>(&sA[r * PITCH + vv * 8]) =
            *reinterpret_cast<const uint4*>(gA + r * KDIM + vv * 8);
        *reinterpret_cast<uint4*>(&sB[r * PITCH + vv * 8]) =
            *reinterpret_cast<const uint4*>(gB + r * KDIM + vv * 8);
    }
    __syncthreads();

    const int lane = tid & 31;
    const int wid  = tid >> 5;
    const int wm   = (wid >> 1) * 32;   // warp row base (0..96)
    const int wn   = (wid & 1) * 64;    // warp col base (0/64)

    float acc[2][8][4];
#pragma unroll
    for (int mt = 0; mt < 2; mt++)
#pragma unroll
        for (int nt = 0; nt < 8; nt++)
#pragma unroll
            for (int i = 0; i < 4; i++) acc[mt][nt][i] = 0.f;

#pragma unroll
    for (int ks = 0; ks < 4; ks++) {
        uint32_t a[2][4];
#pragma unroll
        for (int mt = 0; mt < 2; mt++) {
            int row = wm + mt * 16 + (lane & 15);
            int col = ks * 16 + (lane >> 4) * 8;
            uint32_t addr = (uint32_t)__cvta_generic_to_shared(&sA[row * PITCH + col]);
            asm volatile("ldmatrix.sync.aligned.m8n8.x4.shared.b16 {%0,%1,%2,%3}, [%4];\n"
                         : "=r"(a[mt][0]), "=r"(a[mt][1]), "=r"(a[mt][2]), "=r"(a[mt][3])
                         : "r"(addr));
        }
        uint32_t b[8][2];
#pragma unroll
        for (int nt = 0; nt < 8; nt++) {
            int row = wn + nt * 8 + (lane & 7);
            int col = ks * 16 + ((lane >> 3) & 1) * 8;
            uint32_t addr = (uint32_t)__cvta_generic_to_shared(&sB[row * PITCH + col]);
            asm volatile("ldmatrix.sync.aligned.m8n8.x2.shared.b16 {%0,%1}, [%2];\n"
                         : "=r"(b[nt][0]), "=r"(b[nt][1])
                         : "r"(addr));
        }
#pragma unroll
        for (int mt = 0; mt < 2; mt++)
#pragma unroll
            for (int nt = 0; nt < 8; nt++) {
                asm volatile(
                    "mma.sync.aligned.m16n8k16.row.col.f32.bf16.bf16.f32 "
                    "{%0,%1,%2,%3}, {%4,%5,%6,%7}, {%8,%9}, {%0,%1,%2,%3};\n"
                    : "+f"(acc[mt][nt][0]), "+f"(acc[mt][nt][1]),
                      "+f"(acc[mt][nt][2]), "+f"(acc[mt][nt][3])
                    : "r"(a[mt][0]), "r"(a[mt][1]), "r"(a[mt][2]), "r"(a[mt][3]),
                      "r"(b[nt][0]), "r"(b[nt][1]));
            }
    }

    // Direct global stores: 32B-sector-aligned float2 per lane.
    float* gO = out + (size_t)h * MDIM * NDIM + (size_t)(bm * BM) * NDIM + bn * BN;
#pragma unroll
    for (int mt = 0; mt < 2; mt++) {
#pragma unroll
        for (int nt = 0; nt < 8; nt++) {
            int r0 = wm + mt * 16 + (lane >> 2);
            int c0 = wn + nt * 8 + (lane & 3) * 2;
            *reinterpret_cast<float2*>(&gO[(size_t)r0 * NDIM + c0]) =
                make_float2(acc[mt][nt][0], acc[mt][nt][1]);
            *reinterpret_cast<float2*>(&gO[(size_t)(r0 + 8) * NDIM + c0]) =
                make_float2(acc[mt][nt][2], acc[mt][nt][3]);
        }
    }
}

extern "C" void kernel_launch(void* const* d_in, const int* in_sizes, int n_in,
                              void* d_out, int out_size) {
    (void)in_sizes; (void)n_in; (void)out_size;
    const float* lhs = (const float*)d_in[0];  // [1,16,4096,64]
    const float* rhs = (const float*)d_in[1];  // [1,16,64,4096]
    float* out = (float*)d_out;                // [1,16,4096,4096]

    // 16*4096*2 = 131072 quant blocks each; 2 threads per block.
    quant_lhs_kernel<<<262144 / 256, 256>>>(lhs);
    quant_rhs_kernel<<<262144 / 256, 256>>>(rhs);

    dim3 grid(NDIM / 128, MDIM / 128, HEADS);
    bfp_gemm_kernel<<<grid, 256>>>(out);
}

// round 3
// speedup vs baseline: 1.1018x; 1.0837x over previous
#include <cuda_runtime.h>
#include <cuda_bf16.h>
#include <stdint.h>

#define HEADS 16
#define MDIM 4096
#define NDIM 4096
#define KDIM 64
#define QBLK 32

// Quantized (dequantized-to-bf16, exact) operands. rhs stored transposed: [h][n][k].
static __device__ __nv_bfloat16 g_lhs[(size_t)HEADS * MDIM * KDIM];
static __device__ __nv_bfloat16 g_rhs[(size_t)HEADS * NDIM * KDIM];

// ---------------------------------------------------------------------------
// Half-block (16-element) BFP quantize. Two adjacent threads own one 32-block;
// shared block max via one shfl_xor. All arithmetic exact in fp32
// (power-of-two scaling); results have <=8 significant bits -> exact in bf16.
// ---------------------------------------------------------------------------
__device__ __forceinline__ void quant_half16(float v[16]) {
    float ma = 0.f;
#pragma unroll
    for (int i = 0; i < 16; i++) ma = fmaxf(ma, fabsf(v[i]));
    ma = fmaxf(ma, __shfl_xor_sync(0xFFFFFFFFu, ma, 1));  // full 32-block max
    if (ma > 0.f) {
        int e = ilogbf(fmaxf(ma, 1e-38f));       // floor(log2(.)) exactly
        float scale = exp2f((float)(7 - e));     // exact power of two
        float step  = exp2f((float)(e - 7));
#pragma unroll
        for (int i = 0; i < 16; i++) {
            float q = rintf(v[i] * scale);       // round-half-even
            q = fminf(fmaxf(q, -128.f), 127.f);
            v[i] = q * step;                     // exact
        }
    } else {
#pragma unroll
        for (int i = 0; i < 16; i++) v[i] = 0.f;
    }
}

__device__ __forceinline__ void pack_store16(__nv_bfloat16* dst, const float v[16]) {
    uint32_t pk[8];
#pragma unroll
    for (int j = 0; j < 8; j++) {
        __nv_bfloat162 h2 = __floats2bfloat162_rn(v[2 * j], v[2 * j + 1]);
        pk[j] = *reinterpret_cast<uint32_t*>(&h2);
    }
    uint4* d4 = reinterpret_cast<uint4*>(dst);
    d4[0] = make_uint4(pk[0], pk[1], pk[2], pk[3]);
    d4[1] = make_uint4(pk[4], pk[5], pk[6], pk[7]);
}

// ---------------------------------------------------------------------------
// Fused quant kernel: blocks [0, QL_BLOCKS) handle lhs, the rest handle rhs.
// One launch: both memory patterns (contiguous lhs reads, strided rhs reads)
// run concurrently across the chip; one ramp/drain instead of two.
// ---------------------------------------------------------------------------
#define QL_BLOCKS 1024   // lhs: 262144 threads, 2 per 32-block
#define QR_BLOCKS 1024   // rhs: 262144 threads, 2 per 32-block

__global__ void __launch_bounds__(256) quant_all_kernel(
    const float* __restrict__ lhs, const float* __restrict__ rhs) {
    if (blockIdx.x < QL_BLOCKS) {
        // lhs: [h][m][64] contiguous blocks; thread owns 16 consecutive floats.
        size_t t = blockIdx.x * (size_t)blockDim.x + threadIdx.x;
        const float4* src = reinterpret_cast<const float4*>(lhs + t * 16);
        float v[16];
#pragma unroll
        for (int j = 0; j < 4; j++) {
            float4 f = __ldg(src + j);
            v[4 * j] = f.x; v[4 * j + 1] = f.y; v[4 * j + 2] = f.z; v[4 * j + 3] = f.w;
        }
        quant_half16(v);
        pack_store16(g_lhs + t * 16, v);
    } else {
        // rhs: [h][k=64][n]; blocks along k (stride NDIM). 2 threads per block:
        // same n-column, each covers 16 of 32 k's. Reads coalesced across lanes.
        int t    = (blockIdx.x - QL_BLOCKS) * blockDim.x + threadIdx.x;
        int half = t & 1;
        int pair = t >> 1;
        int c  = pair & (NDIM - 1);
        int kb = (pair >> 12) & 1;
        int h  = pair >> 13;
        const float* src = rhs + ((size_t)h * KDIM + kb * QBLK + half * 16) * NDIM + c;
        float v[16];
#pragma unroll
        for (int k = 0; k < 16; k++) v[k] = __ldg(src + (size_t)k * NDIM);
        quant_half16(v);
        pack_store16(g_rhs + (((size_t)h * NDIM + c) * KDIM + kb * QBLK + half * 16), v);
    }
}

// ---------------------------------------------------------------------------
// GEMM: out[h][m][n] = sum_k A[h][m][k] * B[h][n][k], bf16 in, fp32 out.
// 128x128 tile per CTA, whole K=64 in smem. 8 warps = 4(m) x 2(n), each 32x64.
// Epilogue uses streaming stores (__stcs): output has zero reuse; evict-first
// keeps the L2-resident operand set undisturbed and smooths DRAM eviction.
// ---------------------------------------------------------------------------
__global__ void __launch_bounds__(256, 2) bfp_gemm_kernel(float* __restrict__ out) {
    constexpr int BM = 128, BN = 128, PITCH = 72;  // 144B pitch: conflict-free ldmatrix
    __shared__ __nv_bfloat16 sA[BM * PITCH];
    __shared__ __nv_bfloat16 sB[BN * PITCH];

    const int h  = blockIdx.z;
    const int bm = blockIdx.y, bn = blockIdx.x;
    const __nv_bfloat16* gA = g_lhs + ((size_t)h * MDIM + bm * BM) * KDIM;
    const __nv_bfloat16* gB = g_rhs + ((size_t)h * NDIM + bn * BN) * KDIM;
    const int tid = threadIdx.x;

#pragma unroll
    for (int i = 0; i < 4; i++) {
        int idx = tid + i * 256;
        int r = idx >> 3, vv = idx & 7;
        *reinterpret_cast<uint4*>(&sA[r * PITCH + vv * 8]) =
            *reinterpret_cast<const uint4*>(gA + r * KDIM + vv * 8);
        *reinterpret_cast<uint4*>(&sB[r * PITCH + vv * 8]) =
            *reinterpret_cast<const uint4*>(gB + r * KDIM + vv * 8);
    }
    __syncthreads();

    const int lane = tid & 31;
    const int wid  = tid >> 5;
    const int wm   = (wid >> 1) * 32;   // warp row base (0..96)
    const int wn   = (wid & 1) * 64;    // warp col base (0/64)

    float acc[2][8][4];
#pragma unroll
    for (int mt = 0; mt < 2; mt++)
#pragma unroll
        for (int nt = 0; nt < 8; nt++)
#pragma unroll
            for (int i = 0; i < 4; i++) acc[mt][nt][i] = 0.f;

#pragma unroll
    for (int ks = 0; ks < 4; ks++) {
        uint32_t a[2][4];
#pragma unroll
        for (int mt = 0; mt < 2; mt++) {
            int row = wm + mt * 16 + (lane & 15);
            int col = ks * 16 + (lane >> 4) * 8;
            uint32_t addr = (uint32_t)__cvta_generic_to_shared(&sA[row * PITCH + col]);
            asm volatile("ldmatrix.sync.aligned.m8n8.x4.shared.b16 {%0,%1,%2,%3}, [%4];\n"
                         : "=r"(a[mt][0]), "=r"(a[mt][1]), "=r"(a[mt][2]), "=r"(a[mt][3])
                         : "r"(addr));
        }
        uint32_t b[8][2];
#pragma unroll
        for (int nt = 0; nt < 8; nt++) {
            int row = wn + nt * 8 + (lane & 7);
            int col = ks * 16 + ((lane >> 3) & 1) * 8;
            uint32_t addr = (uint32_t)__cvta_generic_to_shared(&sB[row * PITCH + col]);
            asm volatile("ldmatrix.sync.aligned.m8n8.x2.shared.b16 {%0,%1}, [%2];\n"
                         : "=r"(b[nt][0]), "=r"(b[nt][1])
                         : "r"(addr));
        }
#pragma unroll
        for (int mt = 0; mt < 2; mt++)
#pragma unroll
            for (int nt = 0; nt < 8; nt++) {
                asm volatile(
                    "mma.sync.aligned.m16n8k16.row.col.f32.bf16.bf16.f32 "
                    "{%0,%1,%2,%3}, {%4,%5,%6,%7}, {%8,%9}, {%0,%1,%2,%3};\n"
                    : "+f"(acc[mt][nt][0]), "+f"(acc[mt][nt][1]),
                      "+f"(acc[mt][nt][2]), "+f"(acc[mt][nt][3])
                    : "r"(a[mt][0]), "r"(a[mt][1]), "r"(a[mt][2]), "r"(a[mt][3]),
                      "r"(b[nt][0]), "r"(b[nt][1]));
            }
    }

    // Streaming stores: 32B-sector-aligned float2 per lane, evict-first.
    float* gO = out + (size_t)h * MDIM * NDIM + (size_t)(bm * BM) * NDIM + bn * BN;
#pragma unroll
    for (int mt = 0; mt < 2; mt++) {
#pragma unroll
        for (int nt = 0; nt < 8; nt++) {
            int r0 = wm + mt * 16 + (lane >> 2);
            int c0 = wn + nt * 8 + (lane & 3) * 2;
            __stcs(reinterpret_cast<float2*>(&gO[(size_t)r0 * NDIM + c0]),
                   make_float2(acc[mt][nt][0], acc[mt][nt][1]));
            __stcs(reinterpret_cast<float2*>(&gO[(size_t)(r0 + 8) * NDIM + c0]),
                   make_float2(acc[mt][nt][2], acc[mt][nt][3]));
        }
    }
}

extern "C" void kernel_launch(void* const* d_in, const int* in_sizes, int n_in,
                              void* d_out, int out_size) {
    (void)in_sizes; (void)n_in; (void)out_size;
    const float* lhs = (const float*)d_in[0];  // [1,16,4096,64]
    const float* rhs = (const float*)d_in[1];  // [1,16,64,4096]
    float* out = (float*)d_out;                // [1,16,4096,4096]

    quant_all_kernel<<<QL_BLOCKS + QR_BLOCKS, 256>>>(lhs, rhs);

    dim3 grid(NDIM / 128, MDIM / 128, HEADS);
    bfp_gemm_kernel<<<grid, 256>>>(out);
}